// round 5
// baseline (speedup 1.0000x reference)
#include <cuda_runtime.h>

#define NB   2
#define NN   512
#define IND  512
#define MEMD 300
#define HIDD 64
#define NEG_SLOPE 0.01f
#define GRIDSZ 148
#define NTHR 256

#define BM 32
#define BN 32
#define BK 16
#define TI 32
#define TJ 128

// ---------------- scratch (allocation-free: __device__ globals) -------------
__device__ float g_h[NB * NN * MEMD];
__device__ float g_out1[NB * NN * MEMD];
__device__ float g_s[NB * NN * 128];        // [node][0:64)=si, [64:128)=sj(+a1b)
__device__ float g_a1wp[MEMD * 128];        // packed [k][128] attention weights
__device__ float g_a1bp[128];               // [0...0 | a1b]
__device__ float g_p[NB * NN * NN];
__device__ float g_partial[NB * 64];
__device__ unsigned g_bar_count;            // zero-init
__device__ unsigned g_bar_gen;              // monotonic across replays

// ---------------- grid-wide barrier (replay-safe) ----------------------------
__device__ __forceinline__ void grid_bar(unsigned target)
{
    __threadfence();
    __syncthreads();
    if (threadIdx.x == 0) {
        if (atomicAdd(&g_bar_count, 1u) == GRIDSZ - 1u) {
            g_bar_count = 0u;
            __threadfence();
            *(volatile unsigned*)&g_bar_gen = target;
        } else {
            while ((int)(*(volatile unsigned*)&g_bar_gen - target) < 0) { }
        }
        __threadfence();
    }
    __syncthreads();
}

// ---------------- smem layout ------------------------------------------------
// gemm:  As [16][33] = 2112B | Bs [16][32] = 2048B
// pair:  SiT [64][33] 8448 | SjT [64][129] 33024 | W 256 | red 1024  (=42752)
#define SM_BYTES    44544
#define SM_BS_OFF   2112
#define SM_SJ_OFF   8448
#define SM_W_OFF    (SM_SJ_OFF + 33024)
#define SM_RED_OFF  (SM_W_OFF + 256)
#define SM_INVZ_OFF 43520

// ---------------- tiled GEMM phase: C = scale*(A@B) + bias -------------------
// fma-bound micro: 1 row x 4 cols per thread, float4 B reads, broadcast A.
__device__ void gemm_phase(unsigned char* SM,
                           const float* __restrict__ A, long long sA,
                           const float* __restrict__ Bmat, long long sB,
                           float* __restrict__ C, long long sC,
                           int M, int N, int K,
                           const float* __restrict__ bias,
                           const float* scaleArr, int batches)
{
    float (*As)[BM + 1] = (float(*)[BM + 1])SM;          // [16][33]
    float (*Bs)[BN]     = (float(*)[BN])(SM + SM_BS_OFF); // [16][32]

    int tid = threadIdx.x;
    int tx = tid & 7, ty = tid >> 3;        // compute map: row ty, cols tx*4..+3
    int la_m = tid >> 3;                    // A loader: row, k-pair
    int la_k = (tid & 7) * 2;
    int lb_k = tid >> 4;                    // B loader: k row, col-pair
    int lb_c = (tid & 15) * 2;

    int colT = (N + BN - 1) / BN;
    int rowT = M / BM;
    int T = colT * rowT * batches;

    for (int t = blockIdx.x; t < T; t += GRIDSZ) {
        int bz = t / (colT * rowT);
        int r  = t - bz * colT * rowT;
        int byy = r / colT, bxx = r - byy * colT;
        const float* Ab = A + (long long)bz * sA;
        const float* Bb = Bmat + (long long)bz * sB;
        float* Cb = C + (long long)bz * sC;
        int row0 = byy * BM, col0 = bxx * BN;

        float acc0 = 0.f, acc1 = 0.f, acc2 = 0.f, acc3 = 0.f;

        for (int k0 = 0; k0 < K; k0 += BK) {
            __syncthreads();
            {   // A tile: 32x16, 2 floats/thread (K always even)
                int k = k0 + la_k;
                const float* src = Ab + (long long)(row0 + la_m) * K + k;
                As[la_k][la_m]     = (k     < K) ? src[0] : 0.f;
                As[la_k + 1][la_m] = (k + 1 < K) ? src[1] : 0.f;
            }
            {   // B tile: 16x32, 2 floats/thread (N always even)
                int k = k0 + lb_k;
                int c = col0 + lb_c;
                float v0 = 0.f, v1 = 0.f;
                if (k < K) {
                    if (c + 1 < N) {
                        float2 t2 = *(const float2*)(Bb + (long long)k * N + c);
                        v0 = t2.x; v1 = t2.y;
                    } else if (c < N) {
                        v0 = Bb[(long long)k * N + c];
                    }
                }
                Bs[lb_k][lb_c]     = v0;
                Bs[lb_k][lb_c + 1] = v1;
            }
            __syncthreads();

            #pragma unroll
            for (int kk = 0; kk < BK; kk++) {
                float a = As[kk][ty];
                float4 b = *(const float4*)&Bs[kk][tx * 4];
                acc0 += a * b.x; acc1 += a * b.y;
                acc2 += a * b.z; acc3 += a * b.w;
            }
        }

        float sc = scaleArr ? scaleArr[bz] : 1.f;
        int rr = row0 + ty;
        int c0 = col0 + tx * 4;
        float vals[4] = {acc0, acc1, acc2, acc3};
        #pragma unroll
        for (int c = 0; c < 4; c++) {
            int cc = c0 + c;
            if (cc < N) {
                float v = vals[c] * sc;
                if (bias) v += bias[cc];
                Cb[(long long)rr * N + cc] = v;
            }
        }
    }
}

// ---------------- pack: merge a1w halves + bias vector -----------------------
__device__ void pack_phase(const float* __restrict__ a1w,
                           const float* __restrict__ a1b)
{
    int tid = threadIdx.x;
    for (int idx = blockIdx.x * NTHR + tid; idx < MEMD * 128; idx += GRIDSZ * NTHR) {
        int k = idx >> 7, h2 = idx & 127;
        g_a1wp[idx] = (h2 < 64) ? a1w[k * 64 + h2]
                                : a1w[(MEMD + k) * 64 + (h2 - 64)];
    }
    if (blockIdx.x == 0 && tid < 128)
        g_a1bp[tid] = (tid < 64) ? 0.f : a1b[tid - 64];
}

// ---------------- pairwise: p = adj*exp(leaky(e)), partial Z -----------------
__device__ void pair_phase(unsigned char* SM,
                           const float* __restrict__ adj,
                           const float* __restrict__ a2w,
                           const float* __restrict__ a2b)
{
    float (*SiT)[TI + 1]  = (float(*)[TI + 1])SM;            // [64][33]
    float (*SjT)[TJ + 1]  = (float(*)[TJ + 1])(SM + SM_SJ_OFF); // [64][129]
    float* W   = (float*)(SM + SM_W_OFF);
    float* red = (float*)(SM + SM_RED_OFF);

    int tid = threadIdx.x;
    int tx = tid & 31, ty = tid >> 5;
    const int Tt = NB * (NN / TI) * (NN / TJ);   // 128

    for (int t = blockIdx.x; t < Tt; t += GRIDSZ) {
        int b = t >> 6;
        int rem = t & 63;
        int by = rem >> 2, bx = rem & 3;
        int i0 = by * TI, j0 = bx * TJ;

        __syncthreads();
        for (int idx = tid; idx < HIDD * TI; idx += NTHR) {   // coalesced on h
            int r = idx >> 6, h = idx & 63;
            SiT[h][r] = g_s[((b * NN) + i0 + r) * 128 + h];
        }
        for (int idx = tid; idx < HIDD * TJ; idx += NTHR) {
            int rr = idx >> 6, h = idx & 63;
            SjT[h][rr] = g_s[((b * NN) + j0 + rr) * 128 + 64 + h];
        }
        if (tid < HIDD) W[tid] = a2w[tid];
        __syncthreads();

        float acc[4][4] = {};
        #pragma unroll 8
        for (int h = 0; h < HIDD; h++) {
            float w = W[h];
            float a[4], bb[4];
            #pragma unroll
            for (int ii = 0; ii < 4; ii++) a[ii] = SiT[h][ty + 8 * ii];
            #pragma unroll
            for (int jj = 0; jj < 4; jj++) bb[jj] = SjT[h][tx + 32 * jj];
            #pragma unroll
            for (int ii = 0; ii < 4; ii++)
                #pragma unroll
                for (int jj = 0; jj < 4; jj++) {
                    float x = a[ii] + bb[jj];
                    acc[ii][jj] += fmaxf(x, 0.f) * w;
                }
        }

        float a2bv = a2b[0];
        float psum = 0.f;
        #pragma unroll
        for (int ii = 0; ii < 4; ii++) {
            int i = i0 + ty + 8 * ii;
            #pragma unroll
            for (int jj = 0; jj < 4; jj++) {
                int j = j0 + tx + 32 * jj;
                float e = acc[ii][jj] + a2bv;
                e = e > 0.f ? e : NEG_SLOPE * e;
                float ad = adj[((long long)b * NN + i) * NN + j];
                float pv = ad * __expf(e);
                g_p[((long long)b * NN + i) * NN + j] = pv;
                psum += pv;
            }
        }

        red[tid] = psum;
        __syncthreads();
        for (int s = 128; s > 0; s >>= 1) {
            if (tid < s) red[tid] += red[tid + s];
            __syncthreads();
        }
        if (tid == 0) g_partial[b * 64 + rem] = red[0];
    }
}

// ---------------- invZ (redundant per block) + out = invZ * p@h --------------
__device__ void out_phase(unsigned char* SM, const float* hbuf, float* outbuf)
{
    float* invZ = (float*)(SM + SM_INVZ_OFF);
    int tid = threadIdx.x;
    if (tid < NB) {
        float s = 0.f;
        #pragma unroll
        for (int k = 0; k < 64; k++) s += g_partial[tid * 64 + k];
        invZ[tid] = 1.f / s;
    }
    __syncthreads();
    gemm_phase(SM, g_p, (long long)NN * NN, hbuf, (long long)NN * MEMD,
               outbuf, (long long)NN * MEMD,
               NN, MEMD, NN, nullptr, invZ, NB);
}

// ---------------- the one persistent kernel ----------------------------------
__global__ void __launch_bounds__(NTHR, 1) fused_gat(
    const float* __restrict__ feature, const float* __restrict__ adj,
    const float* __restrict__ w0, const float* __restrict__ b0,
    const float* __restrict__ w1, const float* __restrict__ b1,
    const float* __restrict__ a1w, const float* __restrict__ a1b,
    const float* __restrict__ a2w, const float* __restrict__ a2b,
    float* __restrict__ out)
{
    __shared__ __align__(16) unsigned char SM[SM_BYTES];
    __shared__ unsigned s_base;
    if (threadIdx.x == 0) s_base = *(volatile unsigned*)&g_bar_gen;
    __syncthreads();
    unsigned bb = s_base;

    // -------- layer 1 --------
    pack_phase(a1w, a1b);
    gemm_phase(SM, feature, 0, w0, 0, g_h, 0, NB * NN, MEMD, IND, b0, nullptr, 1);
    grid_bar(bb + 1);
    gemm_phase(SM, g_h, 0, g_a1wp, 0, g_s, 0, NB * NN, 128, MEMD, g_a1bp, nullptr, 1);
    grid_bar(bb + 2);
    pair_phase(SM, adj, a2w, a2b);
    grid_bar(bb + 3);
    out_phase(SM, g_h, g_out1);
    grid_bar(bb + 4);

    // -------- layer 2 --------
    gemm_phase(SM, g_out1, 0, w1, 0, g_h, 0, NB * NN, MEMD, MEMD, b1, nullptr, 1);
    grid_bar(bb + 5);
    gemm_phase(SM, g_h, 0, g_a1wp, 0, g_s, 0, NB * NN, 128, MEMD, g_a1bp, nullptr, 1);
    grid_bar(bb + 6);
    pair_phase(SM, adj, a2w, a2b);
    grid_bar(bb + 7);
    out_phase(SM, g_h, out);
}

// ---------------- host launcher ----------------------------------------------
extern "C" void kernel_launch(void* const* d_in, const int* in_sizes, int n_in,
                              void* d_out, int out_size)
{
    const float* feature = (const float*)d_in[0];
    const float* adj     = (const float*)d_in[1];
    const float* w0      = (const float*)d_in[2];
    const float* b0      = (const float*)d_in[3];
    const float* w1      = (const float*)d_in[4];
    const float* b1      = (const float*)d_in[5];
    const float* a1w     = (const float*)d_in[6];
    const float* a1b     = (const float*)d_in[7];
    const float* a2w     = (const float*)d_in[8];
    const float* a2b     = (const float*)d_in[9];
    float* out = (float*)d_out;

    fused_gat<<<GRIDSZ, NTHR>>>(feature, adj, w0, b0, w1, b1,
                                a1w, a1b, a2w, a2b, out);
}

// round 6
// speedup vs baseline: 1.5399x; 1.5399x over previous
#include <cuda_runtime.h>

#define NB   2
#define NN   512
#define IND  512
#define MEMD 300
#define HIDD 64
#define NEG_SLOPE 0.01f
#define GRIDSZ 148
#define NTHR 512

#define BM 32
#define BN 64
#define BK 16
#define TI 32
#define TJ 128

// ---------------- scratch (allocation-free: __device__ globals) -------------
__device__ float g_h[NB * NN * MEMD];
__device__ float g_out1[NB * NN * MEMD];
__device__ float g_s[NB * NN * 128];        // [node][0:64)=si, [64:128)=sj(+a1b)
__device__ float g_a1wp[MEMD * 128];        // packed [k][128] attention weights
__device__ float g_a1bp[128];               // [0...0 | a1b]
__device__ float g_p[NB * NN * NN];
__device__ float g_partial[NB * 64];
__device__ unsigned g_bar_count;            // zero-init
__device__ unsigned g_bar_gen;              // monotonic across replays

// ---------------- grid-wide barrier (replay-safe) ----------------------------
__device__ __forceinline__ void grid_bar(unsigned target)
{
    __threadfence();
    __syncthreads();
    if (threadIdx.x == 0) {
        if (atomicAdd(&g_bar_count, 1u) == GRIDSZ - 1u) {
            g_bar_count = 0u;
            __threadfence();
            *(volatile unsigned*)&g_bar_gen = target;
        } else {
            while ((int)(*(volatile unsigned*)&g_bar_gen - target) < 0) { }
        }
        __threadfence();
    }
    __syncthreads();
}

// per-half named barrier (256 threads each; ids 1,2)
__device__ __forceinline__ void half_bar(int half)
{
    asm volatile("bar.sync %0, 256;" :: "r"(half + 1) : "memory");
}

// ---------------- smem layout ------------------------------------------------
// gemm (per half, 12544B): As2 [2][16][17] float2 = 4352B | Bs [2][16][64] = 8192B
// pair: SiT2 [64][17] float2 = 8704 | SjT [64][129] = 33024 | W 256 | red 2048
// invZ @ 44032
#define SM_BYTES     44160
#define SM_HALF_SZ   12544
#define SM_BS_OFF    4352
#define SM_SJ_OFF    8704
#define SM_W_OFF     (SM_SJ_OFF + 33024)
#define SM_RED_OFF   (SM_W_OFF + 256)
#define SM_INVZ_OFF  44032

// ---------------- half-block GEMM: C = scale*(A@B) + bias --------------------
// each 256-thread half computes its own 32x64 tiles, 2x4 micro, double-buffered
__device__ void gemm_half(unsigned char* SM, int half,
                          const float* __restrict__ A, long long sA,
                          const float* __restrict__ Bmat, long long sB,
                          float* __restrict__ C, long long sC,
                          int M, int N, int K,
                          const float* __restrict__ bias,
                          const float* scaleArr, int batches)
{
    unsigned char* base = SM + half * SM_HALF_SZ;
    float2 (*As2)[BK][17] = (float2(*)[BK][17])base;              // [2][16][17]
    float  (*Bs)[BK][BN]  = (float(*)[BK][BN])(base + SM_BS_OFF); // [2][16][64]

    int lid = threadIdx.x & 255;
    int tx = lid & 15, ty = lid >> 4;          // compute: rows ty,ty+16; cols tx*4..+3
    int ak = lid & 15, ar = lid >> 4;          // A loader: k=ak, row pair (ar, ar+16)
    int bc = (lid & 31) * 2, bk = lid >> 5;    // B loader: col pair bc, rows bk, bk+8

    int colT = (N + BN - 1) / BN;
    int rowT = M / BM;
    int T = colT * rowT * batches;
    int nkt = (K + BK - 1) / BK;

    for (int t = half * GRIDSZ + blockIdx.x; t < T; t += 2 * GRIDSZ) {
        int bz  = t / (colT * rowT);
        int r   = t - bz * colT * rowT;
        int byy = r / colT, bxx = r - byy * colT;
        const float* Ab = A + (long long)bz * sA;
        const float* Bb = Bmat + (long long)bz * sB;
        float* Cb = C + (long long)bz * sC;
        int row0 = byy * BM, col0 = bxx * BN;
        int cB = col0 + bc;
        bool cok = (cB < N);                 // N even, bc even -> cB+1 < N too

        // ---- prologue: k-tile 0 directly to smem buf 0 (K >= 16 always)
        {
            float a0 = Ab[(row0 + ar) * K + ak];
            float a1 = Ab[(row0 + ar + 16) * K + ak];
            As2[0][ak][ar] = make_float2(a0, a1);
            float2 b0 = make_float2(0.f, 0.f), b1 = make_float2(0.f, 0.f);
            if (cok) {
                b0 = *(const float2*)&Bb[(long long)bk * N + cB];
                b1 = *(const float2*)&Bb[(long long)(bk + 8) * N + cB];
            }
            *(float2*)&Bs[0][bk][bc]     = b0;
            *(float2*)&Bs[0][bk + 8][bc] = b1;
        }
        half_bar(half);

        float acc[8] = {0.f, 0.f, 0.f, 0.f, 0.f, 0.f, 0.f, 0.f};

        for (int kt = 0; kt < nkt; kt++) {
            int buf = kt & 1;

            // ---- prefetch k-tile kt+1 into registers (clamped addresses)
            float pa0 = 0.f, pa1 = 0.f;
            float2 pb0 = make_float2(0.f, 0.f), pb1 = make_float2(0.f, 0.f);
            bool more = (kt + 1 < nkt);
            if (more) {
                int k  = (kt + 1) * BK + ak;
                int kc = k < K ? k : K - 1;
                pa0 = Ab[(row0 + ar) * K + kc];
                pa1 = Ab[(row0 + ar + 16) * K + kc];
                if (k >= K) { pa0 = 0.f; pa1 = 0.f; }
                int k0 = (kt + 1) * BK + bk, k1 = k0 + 8;
                if (cok) {
                    int k0c = k0 < K ? k0 : K - 1;
                    int k1c = k1 < K ? k1 : K - 1;
                    pb0 = *(const float2*)&Bb[(long long)k0c * N + cB];
                    pb1 = *(const float2*)&Bb[(long long)k1c * N + cB];
                }
                if (k0 >= K) pb0 = make_float2(0.f, 0.f);
                if (k1 >= K) pb1 = make_float2(0.f, 0.f);
            }

            // ---- compute current buffer
            #pragma unroll
            for (int kk = 0; kk < BK; kk++) {
                float2 a = As2[buf][kk][ty];
                float4 b = *(const float4*)&Bs[buf][kk][tx * 4];
                acc[0] += a.x * b.x; acc[1] += a.x * b.y;
                acc[2] += a.x * b.z; acc[3] += a.x * b.w;
                acc[4] += a.y * b.x; acc[5] += a.y * b.y;
                acc[6] += a.y * b.z; acc[7] += a.y * b.w;
            }

            // ---- commit prefetch to the other buffer
            if (more) {
                As2[buf ^ 1][ak][ar] = make_float2(pa0, pa1);
                *(float2*)&Bs[buf ^ 1][bk][bc]     = pb0;
                *(float2*)&Bs[buf ^ 1][bk + 8][bc] = pb1;
            }
            half_bar(half);
        }

        // ---- epilogue
        float sc = scaleArr ? scaleArr[bz] : 1.f;
        int c0 = col0 + tx * 4;
        int r0 = row0 + ty, r1 = row0 + ty + 16;
        #pragma unroll
        for (int j = 0; j < 4; j++) {
            int cc = c0 + j;
            if (cc < N) {
                float bv = bias ? bias[cc] : 0.f;
                Cb[(long long)r0 * N + cc] = acc[j]     * sc + bv;
                Cb[(long long)r1 * N + cc] = acc[4 + j] * sc + bv;
            }
        }
    }
}

// ---------------- pack: merge a1w halves + bias vector -----------------------
__device__ void pack_phase(const float* __restrict__ a1w,
                           const float* __restrict__ a1b)
{
    int tid = threadIdx.x;
    for (int idx = blockIdx.x * NTHR + tid; idx < MEMD * 128; idx += GRIDSZ * NTHR) {
        int k = idx >> 7, h2 = idx & 127;
        g_a1wp[idx] = (h2 < 64) ? a1w[k * 64 + h2]
                                : a1w[(MEMD + k) * 64 + (h2 - 64)];
    }
    if (blockIdx.x == 0 && tid < 128)
        g_a1bp[tid] = (tid < 64) ? 0.f : a1b[tid - 64];
}

// ---------------- pairwise: p = adj*exp(leaky(e)), partial Z -----------------
__device__ void pair_phase(unsigned char* SM,
                           const float* __restrict__ adj,
                           const float* __restrict__ a2w,
                           const float* __restrict__ a2b)
{
    float2 (*SiT2)[17]    = (float2(*)[17])SM;                 // [64][17]
    float  (*SjT)[TJ + 1] = (float(*)[TJ + 1])(SM + SM_SJ_OFF); // [64][129]
    float* W   = (float*)(SM + SM_W_OFF);
    float* red = (float*)(SM + SM_RED_OFF);

    int tid = threadIdx.x;
    int tx = tid & 31, ty = (tid >> 5) & 15;   // warp-uniform ty per warp
    const int Tt = NB * (NN / TI) * (NN / TJ); // 128

    for (int t = blockIdx.x; t < Tt; t += GRIDSZ) {
        int b = t >> 6;
        int rem = t & 63;
        int by = rem >> 2, bx = rem & 3;
        int i0 = by * TI, j0 = bx * TJ;

        __syncthreads();
        for (int idx = tid; idx < HIDD * 16; idx += NTHR) {   // 1024 / 512
            int h = idx & 63, rr = idx >> 6;
            float v0 = g_s[((b * NN) + i0 + rr) * 128 + h];
            float v1 = g_s[((b * NN) + i0 + rr + 16) * 128 + h];
            SiT2[h][rr] = make_float2(v0, v1);
        }
        for (int idx = tid; idx < HIDD * TJ; idx += NTHR) {
            int h = idx & 63, rr = idx >> 6;
            SjT[h][rr] = g_s[((b * NN) + j0 + rr) * 128 + 64 + h];
        }
        if (tid < HIDD) W[tid] = a2w[tid];
        __syncthreads();

        float acc[8] = {0.f, 0.f, 0.f, 0.f, 0.f, 0.f, 0.f, 0.f};
        #pragma unroll 8
        for (int h = 0; h < HIDD; h++) {
            float w = W[h];
            float2 ai = SiT2[h][ty];
            float bj[4];
            #pragma unroll
            for (int jj = 0; jj < 4; jj++) bj[jj] = SjT[h][tx + 32 * jj];
            #pragma unroll
            for (int jj = 0; jj < 4; jj++) {
                float x0 = ai.x + bj[jj];
                float x1 = ai.y + bj[jj];
                acc[jj]     += fmaxf(x0, 0.f) * w;
                acc[4 + jj] += fmaxf(x1, 0.f) * w;
            }
        }

        float a2bv = a2b[0];
        float psum = 0.f;
        int i0a = i0 + ty, i0b = i0 + ty + 16;
        #pragma unroll
        for (int jj = 0; jj < 4; jj++) {
            int j = j0 + tx + 32 * jj;
            float e0 = acc[jj] + a2bv;
            float e1 = acc[4 + jj] + a2bv;
            e0 = e0 > 0.f ? e0 : NEG_SLOPE * e0;
            e1 = e1 > 0.f ? e1 : NEG_SLOPE * e1;
            float ad0 = adj[((long long)b * NN + i0a) * NN + j];
            float ad1 = adj[((long long)b * NN + i0b) * NN + j];
            float p0 = ad0 * __expf(e0);
            float p1 = ad1 * __expf(e1);
            g_p[((long long)b * NN + i0a) * NN + j] = p0;
            g_p[((long long)b * NN + i0b) * NN + j] = p1;
            psum += p0 + p1;
        }

        red[tid] = psum;
        __syncthreads();
        for (int s = 256; s > 0; s >>= 1) {
            if (tid < s) red[tid] += red[tid + s];
            __syncthreads();
        }
        if (tid == 0) g_partial[b * 64 + rem] = red[0];
    }
}

// ---------------- invZ (redundant per block) + out = invZ * p@h --------------
__device__ void out_phase(unsigned char* SM, int half,
                          const float* hbuf, float* outbuf)
{
    float* invZ = (float*)(SM + SM_INVZ_OFF);
    int tid = threadIdx.x;
    if (tid < NB) {
        float s = 0.f;
        #pragma unroll
        for (int k = 0; k < 64; k++) s += g_partial[tid * 64 + k];
        invZ[tid] = 1.f / s;
    }
    __syncthreads();
    gemm_half(SM, half, g_p, (long long)NN * NN, hbuf, (long long)NN * MEMD,
              outbuf, (long long)NN * MEMD, NN, MEMD, NN, nullptr, invZ, NB);
}

// ---------------- the one persistent kernel ----------------------------------
__global__ void __launch_bounds__(NTHR, 1) fused_gat(
    const float* __restrict__ feature, const float* __restrict__ adj,
    const float* __restrict__ w0, const float* __restrict__ b0,
    const float* __restrict__ w1, const float* __restrict__ b1,
    const float* __restrict__ a1w, const float* __restrict__ a1b,
    const float* __restrict__ a2w, const float* __restrict__ a2b,
    float* __restrict__ out)
{
    __shared__ __align__(16) unsigned char SM[SM_BYTES];
    __shared__ unsigned s_base;
    if (threadIdx.x == 0) s_base = *(volatile unsigned*)&g_bar_gen;
    __syncthreads();
    unsigned bb = s_base;
    int half = threadIdx.x >> 8;

    // -------- layer 1 --------
    pack_phase(a1w, a1b);
    gemm_half(SM, half, feature, 0, w0, 0, g_h, 0, NB * NN, MEMD, IND, b0, nullptr, 1);
    grid_bar(bb + 1);
    gemm_half(SM, half, g_h, 0, g_a1wp, 0, g_s, 0, NB * NN, 128, MEMD, g_a1bp, nullptr, 1);
    grid_bar(bb + 2);
    pair_phase(SM, adj, a2w, a2b);
    grid_bar(bb + 3);
    out_phase(SM, half, g_h, g_out1);
    grid_bar(bb + 4);

    // -------- layer 2 --------
    gemm_half(SM, half, g_out1, 0, w1, 0, g_h, 0, NB * NN, MEMD, MEMD, b1, nullptr, 1);
    grid_bar(bb + 5);
    gemm_half(SM, half, g_h, 0, g_a1wp, 0, g_s, 0, NB * NN, 128, MEMD, g_a1bp, nullptr, 1);
    grid_bar(bb + 6);
    pair_phase(SM, adj, a2w, a2b);
    grid_bar(bb + 7);
    out_phase(SM, half, g_h, out);
}

// ---------------- host launcher ----------------------------------------------
extern "C" void kernel_launch(void* const* d_in, const int* in_sizes, int n_in,
                              void* d_out, int out_size)
{
    const float* feature = (const float*)d_in[0];
    const float* adj     = (const float*)d_in[1];
    const float* w0      = (const float*)d_in[2];
    const float* b0      = (const float*)d_in[3];
    const float* w1      = (const float*)d_in[4];
    const float* b1      = (const float*)d_in[5];
    const float* a1w     = (const float*)d_in[6];
    const float* a1b     = (const float*)d_in[7];
    const float* a2w     = (const float*)d_in[8];
    const float* a2b     = (const float*)d_in[9];
    float* out = (float*)d_out;

    fused_gat<<<GRIDSZ, NTHR>>>(feature, adj, w0, b0, w1, b1,
                                a1w, a1b, a2w, a2b, out);
}

// round 7
// speedup vs baseline: 1.7819x; 1.1572x over previous
#include <cuda_runtime.h>

#define NB   2
#define NN   512
#define IND  512
#define MEMD 300
#define HIDD 64
#define CDIM 428            // 300 + 128 combined output width
#define NEG_SLOPE 0.01f
#define GRIDSZ 148
#define NTHR 512
#define TI 32
#define TJ 128

// ---------------- scratch (allocation-free: __device__ globals) -------------
__device__ float g_B1[IND * CDIM];        // [w0 | Wp0]  (512 x 428)
__device__ float g_B2[MEMD * CDIM];       // [w1 | Wp1]  (300 x 428)
__device__ float g_bias1[CDIM];
__device__ float g_bias2[CDIM];
__device__ float g_hs[NB * NN * CDIM];    // [h(300) | si(64) | sj(64)] per node
__device__ float g_out1[NB * NN * MEMD];  // layer-1 output
__device__ float g_p[NB * NN * NN];
__device__ float g_partial[NB * 64];
__device__ unsigned g_bar_count;          // zero-init
__device__ unsigned g_bar_gen;            // monotonic across replays

// ---------------- grid-wide barrier (replay-safe) ----------------------------
__device__ __forceinline__ void grid_bar(unsigned target)
{
    __threadfence();
    __syncthreads();
    if (threadIdx.x == 0) {
        if (atomicAdd(&g_bar_count, 1u) == GRIDSZ - 1u) {
            g_bar_count = 0u;
            __threadfence();
            *(volatile unsigned*)&g_bar_gen = target;
        } else {
            while ((int)(*(volatile unsigned*)&g_bar_gen - target) < 0) { }
        }
        __threadfence();
    }
    __syncthreads();
}

__device__ __forceinline__ void half_bar(int half)
{
    asm volatile("bar.sync %0, 256;" :: "r"(half + 1) : "memory");
}

// ---------------- dynamic smem layout ----------------------------------------
// gemm per half (25088B): As2 float2[2][32][17]=8704 | Bs float[2][32][64]=16384
// pair: SiT2 f2[64][17]=8704 | SjT [64][129]=33024 | W 256 | red 2048 (=44032)
// invZ at 50176
#define SM_HALF  25088
#define SM_BS    8704
#define SM_SJ    8704
#define SM_W     41728
#define SM_RED   41984
#define SM_INVZ  50176
#define SM_DYN   50304

// ---------------- B fetch modes ----------------------------------------------
// mode 0: plain row-major B[k*ldB + c]
// mode 1: a1w packed view: c<64 -> a1w[k*64+c], else a1w[(300+k)*64 + c-64]
template<int BMODE>
__device__ __forceinline__ float2 bfetch(const float* __restrict__ B,
                                         int k, int c, int ldB)
{
    if (BMODE == 0)
        return *(const float2*)&B[(long long)k * ldB + c];
    else
        return (c < 64) ? *(const float2*)&B[k * 64 + c]
                        : *(const float2*)&B[(MEMD + k) * 64 + (c - 64)];
}

// ---------------- half-stream GEMM: C = scale*(A@B) + bias -------------------
// 256-thread half computes 32x64 tiles, BK=32, 2x4 micro, double-buffered.
template<int BMODE>
__device__ void gemm_half(char* SMD, int half, int ghalf,
                          const float* __restrict__ A, long long strideA,
                          const float* __restrict__ B, long long strideB,
                          float* __restrict__ C, long long strideC,
                          int M, int Ncols, int K,
                          int ldA, int ldB, int ldC,
                          const float* __restrict__ bias,
                          const float* scaleArr, int batches)
{
    char* base = SMD + half * SM_HALF;
    float2 (*As2)[32][17] = (float2(*)[32][17])base;
    float  (*Bs)[32][64]  = (float(*)[32][64])(base + SM_BS);

    int lid = threadIdx.x & 255;
    int tx = lid & 15, ty = lid >> 4;        // compute: rows ty,ty+16; cols tx*4
    int ak = lid & 31, ar = lid >> 5;        // A loader: k=ak, rows ar, ar+8 (+16)
    int bc = (lid & 31) * 2, bk = lid >> 5;  // B loader: col pair, k rows bk+8q

    int colT = (Ncols + 63) >> 6;
    int rowT = (M + 31) >> 5;
    int TT = colT * rowT * batches;
    int nkt = (K + 31) >> 5;

    for (int t = ghalf; t < TT; t += 2 * GRIDSZ) {
        int bz  = t / (colT * rowT);
        int r   = t - bz * colT * rowT;
        int byy = r / colT, bxx = r - byy * colT;
        const float* Ab = A + (long long)bz * strideA;
        const float* Bb = B + (long long)bz * strideB;
        float* Cb = C + (long long)bz * strideC;
        int row0 = byy * 32, col0 = bxx * 64;

        int ra0 = row0 + ar, ra1 = row0 + ar + 8;
        int ccB = col0 + bc;
        bool cok = ccB < Ncols;

        // ---- prologue: ktile 0 -> buf 0
        {
            float a00 = 0.f, a01 = 0.f, a10 = 0.f, a11 = 0.f;
            if (ra0      < M) a00 = Ab[(long long)ra0        * ldA + ak];
            if (ra0 + 16 < M) a01 = Ab[(long long)(ra0 + 16) * ldA + ak];
            if (ra1      < M) a10 = Ab[(long long)ra1        * ldA + ak];
            if (ra1 + 16 < M) a11 = Ab[(long long)(ra1 + 16) * ldA + ak];
            As2[0][ak][ar]     = make_float2(a00, a01);
            As2[0][ak][ar + 8] = make_float2(a10, a11);
            #pragma unroll
            for (int q = 0; q < 4; q++) {
                int kk = bk + 8 * q;
                float2 v = make_float2(0.f, 0.f);
                if (cok && kk < K) v = bfetch<BMODE>(Bb, kk, ccB, ldB);
                *(float2*)&Bs[0][kk][bc] = v;
            }
        }
        half_bar(half);

        float acc[8] = {0.f, 0.f, 0.f, 0.f, 0.f, 0.f, 0.f, 0.f};

        for (int kt = 0; kt < nkt; kt++) {
            int buf = kt & 1;
            bool more = (kt + 1 < nkt);

            // ---- prefetch ktile kt+1 into registers
            float pa0 = 0.f, pa1 = 0.f, pa2 = 0.f, pa3 = 0.f;
            float2 pb[4];
            #pragma unroll
            for (int q = 0; q < 4; q++) pb[q] = make_float2(0.f, 0.f);
            if (more) {
                int k = (kt + 1) * 32 + ak;
                if (k < K) {
                    if (ra0      < M) pa0 = Ab[(long long)ra0        * ldA + k];
                    if (ra0 + 16 < M) pa1 = Ab[(long long)(ra0 + 16) * ldA + k];
                    if (ra1      < M) pa2 = Ab[(long long)ra1        * ldA + k];
                    if (ra1 + 16 < M) pa3 = Ab[(long long)(ra1 + 16) * ldA + k];
                }
                #pragma unroll
                for (int q = 0; q < 4; q++) {
                    int kk = (kt + 1) * 32 + bk + 8 * q;
                    if (cok && kk < K) pb[q] = bfetch<BMODE>(Bb, kk, ccB, ldB);
                }
            }

            // ---- compute current buffer
            #pragma unroll
            for (int kk = 0; kk < 32; kk++) {
                float2 a  = As2[buf][kk][ty];
                float4 b4 = *(const float4*)&Bs[buf][kk][tx * 4];
                acc[0] += a.x * b4.x; acc[1] += a.x * b4.y;
                acc[2] += a.x * b4.z; acc[3] += a.x * b4.w;
                acc[4] += a.y * b4.x; acc[5] += a.y * b4.y;
                acc[6] += a.y * b4.z; acc[7] += a.y * b4.w;
            }

            // ---- commit prefetch
            if (more) {
                As2[buf ^ 1][ak][ar]     = make_float2(pa0, pa1);
                As2[buf ^ 1][ak][ar + 8] = make_float2(pa2, pa3);
                #pragma unroll
                for (int q = 0; q < 4; q++)
                    *(float2*)&Bs[buf ^ 1][bk + 8 * q][bc] = pb[q];
            }
            half_bar(half);
        }

        // ---- epilogue
        float sc = scaleArr ? scaleArr[bz] : 1.f;
        int c0 = col0 + tx * 4;
        int r0c = row0 + ty, r1c = row0 + ty + 16;
        #pragma unroll
        for (int j = 0; j < 4; j++) {
            int cc = c0 + j;
            if (cc < Ncols) {
                float bv = bias ? bias[cc] : 0.f;
                if (r0c < M) Cb[(long long)r0c * ldC + cc] = acc[j]     * sc + bv;
                if (r1c < M) Cb[(long long)r1c * ldC + cc] = acc[4 + j] * sc + bv;
            }
        }
    }
}

// ---------------- pairwise: p = adj*exp(leaky(e)), partial Z -----------------
__device__ void pair_phase(char* SMD,
                           const float* __restrict__ adj,
                           const float* __restrict__ a2w,
                           const float* __restrict__ a2b)
{
    float2 (*SiT2)[17]    = (float2(*)[17])SMD;                  // [64][17]
    float  (*SjT)[TJ + 1] = (float(*)[TJ + 1])(SMD + SM_SJ);     // [64][129]
    float* W   = (float*)(SMD + SM_W);
    float* red = (float*)(SMD + SM_RED);

    int tid = threadIdx.x;
    int tx = tid & 31, ty = (tid >> 5) & 15;
    const int Tt = NB * (NN / TI) * (NN / TJ);   // 128

    for (int t = blockIdx.x; t < Tt; t += GRIDSZ) {
        int b = t >> 6;
        int rem = t & 63;
        int by = rem >> 2, bx = rem & 3;
        int i0 = by * TI, j0 = bx * TJ;

        __syncthreads();
        for (int idx = tid; idx < HIDD * 16; idx += NTHR) {
            int h = idx & 63, rr = idx >> 6;
            float v0 = g_hs[((long long)(b * NN) + i0 + rr) * CDIM + 300 + h];
            float v1 = g_hs[((long long)(b * NN) + i0 + rr + 16) * CDIM + 300 + h];
            SiT2[h][rr] = make_float2(v0, v1);
        }
        for (int idx = tid; idx < HIDD * TJ; idx += NTHR) {
            int h = idx & 63, rr = idx >> 6;
            SjT[h][rr] = g_hs[((long long)(b * NN) + j0 + rr) * CDIM + 364 + h];
        }
        if (tid < HIDD) W[tid] = a2w[tid];
        __syncthreads();

        float acc[8] = {0.f, 0.f, 0.f, 0.f, 0.f, 0.f, 0.f, 0.f};
        #pragma unroll 8
        for (int h = 0; h < HIDD; h++) {
            float w = W[h];
            float2 ai = SiT2[h][ty];
            float bj[4];
            #pragma unroll
            for (int jj = 0; jj < 4; jj++) bj[jj] = SjT[h][tx + 32 * jj];
            #pragma unroll
            for (int jj = 0; jj < 4; jj++) {
                float x0 = ai.x + bj[jj];
                float x1 = ai.y + bj[jj];
                acc[jj]     += fmaxf(x0, 0.f) * w;
                acc[4 + jj] += fmaxf(x1, 0.f) * w;
            }
        }

        float a2bv = a2b[0];
        float psum = 0.f;
        int ia = i0 + ty, ib = i0 + ty + 16;
        #pragma unroll
        for (int jj = 0; jj < 4; jj++) {
            int j = j0 + tx + 32 * jj;
            float e0 = acc[jj] + a2bv;
            float e1 = acc[4 + jj] + a2bv;
            e0 = e0 > 0.f ? e0 : NEG_SLOPE * e0;
            e1 = e1 > 0.f ? e1 : NEG_SLOPE * e1;
            float ad0 = adj[((long long)b * NN + ia) * NN + j];
            float ad1 = adj[((long long)b * NN + ib) * NN + j];
            float p0 = ad0 * __expf(e0);
            float p1 = ad1 * __expf(e1);
            g_p[((long long)b * NN + ia) * NN + j] = p0;
            g_p[((long long)b * NN + ib) * NN + j] = p1;
            psum += p0 + p1;
        }

        red[tid] = psum;
        __syncthreads();
        for (int s = 256; s > 0; s >>= 1) {
            if (tid < s) red[tid] += red[tid + s];
            __syncthreads();
        }
        if (tid == 0) g_partial[b * 64 + rem] = red[0];
    }
}

// ---------------- out = invZ * (p @ h) ---------------------------------------
__device__ void out_phase(char* SMD, int half, int ghalf, float* outbuf, int ldO)
{
    float* invZ = (float*)(SMD + SM_INVZ);
    int tid = threadIdx.x;
    if (tid < NB) {
        float s = 0.f;
        #pragma unroll
        for (int k = 0; k < 64; k++) s += g_partial[tid * 64 + k];
        invZ[tid] = 1.f / s;
    }
    __syncthreads();
    gemm_half<0>(SMD, half, ghalf,
                 g_p, (long long)NN * NN,
                 g_hs, (long long)NN * CDIM,
                 outbuf, (long long)NN * ldO,
                 NN, MEMD, NN, NN, CDIM, ldO, nullptr, invZ, NB);
}

// ---------------- the one persistent kernel ----------------------------------
__global__ void __launch_bounds__(NTHR, 1) fused_gat(
    const float* __restrict__ feature, const float* __restrict__ adj,
    const float* __restrict__ w0, const float* __restrict__ b0,
    const float* __restrict__ w1, const float* __restrict__ b1,
    const float* __restrict__ a1w, const float* __restrict__ a1b,
    const float* __restrict__ a2w, const float* __restrict__ a2b,
    float* __restrict__ out)
{
    extern __shared__ char SMD[];
    __shared__ unsigned s_base;
    if (threadIdx.x == 0) s_base = *(volatile unsigned*)&g_bar_gen;
    __syncthreads();
    unsigned bb = s_base;
    int half  = threadIdx.x >> 8;
    int ghalf = half * GRIDSZ + blockIdx.x;   // 0..295
    int tid = threadIdx.x;

    // ======== P0: build B' = [W | W@a1wp] and bias vectors ========
    for (int idx = blockIdx.x * NTHR + tid; idx < IND * MEMD; idx += GRIDSZ * NTHR) {
        int r = idx / MEMD, c = idx - r * MEMD;
        g_B1[r * CDIM + c] = w0[idx];
    }
    for (int idx = blockIdx.x * NTHR + tid; idx < MEMD * MEMD; idx += GRIDSZ * NTHR) {
        int r = idx / MEMD, c = idx - r * MEMD;
        g_B2[r * CDIM + c] = w1[idx];
    }
    if (blockIdx.x < 2) {
        const float* bsrc = blockIdx.x ? b1 : b0;
        float* bd = blockIdx.x ? g_bias2 : g_bias1;
        for (int c = tid; c < MEMD; c += NTHR) bd[c] = bsrc[c];
        if (tid < 128) {
            float acc = 0.f;
            for (int k = 0; k < MEMD; k++) {
                float w = (tid < 64) ? a1w[k * 64 + tid]
                                     : a1w[(MEMD + k) * 64 + (tid - 64)];
                acc += bsrc[k] * w;
            }
            bd[300 + tid] = acc + ((tid >= 64) ? a1b[tid - 64] : 0.f);
        }
    }
    // Wp0 on halves 0..31 ; Wp1 on halves 295..276 (disjoint, concurrent)
    gemm_half<1>(SMD, half, ghalf, w0, 0, a1w, 0, g_B1 + 300, 0,
                 IND, 128, MEMD, MEMD, 64, CDIM, nullptr, nullptr, 1);
    gemm_half<1>(SMD, half, 295 - ghalf, w1, 0, a1w, 0, g_B2 + 300, 0,
                 MEMD, 128, MEMD, MEMD, 64, CDIM, nullptr, nullptr, 1);
    grid_bar(bb + 1);

    // ======== layer 1 ========
    gemm_half<0>(SMD, half, ghalf, feature, 0, g_B1, 0, g_hs, 0,
                 NB * NN, CDIM, IND, IND, CDIM, CDIM, g_bias1, nullptr, 1);
    grid_bar(bb + 2);
    pair_phase(SMD, adj, a2w, a2b);
    grid_bar(bb + 3);
    out_phase(SMD, half, ghalf, g_out1, MEMD);
    grid_bar(bb + 4);

    // ======== layer 2 ========
    gemm_half<0>(SMD, half, ghalf, g_out1, 0, g_B2, 0, g_hs, 0,
                 NB * NN, CDIM, MEMD, MEMD, CDIM, CDIM, g_bias2, nullptr, 1);
    grid_bar(bb + 5);
    pair_phase(SMD, adj, a2w, a2b);
    grid_bar(bb + 6);
    out_phase(SMD, half, ghalf, out, MEMD);
}

// ---------------- host launcher ----------------------------------------------
extern "C" void kernel_launch(void* const* d_in, const int* in_sizes, int n_in,
                              void* d_out, int out_size)
{
    const float* feature = (const float*)d_in[0];
    const float* adj     = (const float*)d_in[1];
    const float* w0      = (const float*)d_in[2];
    const float* b0      = (const float*)d_in[3];
    const float* w1      = (const float*)d_in[4];
    const float* b1      = (const float*)d_in[5];
    const float* a1w     = (const float*)d_in[6];
    const float* a1b     = (const float*)d_in[7];
    const float* a2w     = (const float*)d_in[8];
    const float* a2b     = (const float*)d_in[9];
    float* out = (float*)d_out;

    static bool attr_set = false;
    if (!attr_set) {
        cudaFuncSetAttribute(fused_gat,
                             cudaFuncAttributeMaxDynamicSharedMemorySize, SM_DYN);
        attr_set = true;
    }
    fused_gat<<<GRIDSZ, NTHR, SM_DYN>>>(feature, adj, w0, b0, w1, b1,
                                        a1w, a1b, a2w, a2b, out);
}

// round 9
// speedup vs baseline: 1.9283x; 1.0822x over previous
#include <cuda_runtime.h>

typedef unsigned int       u32;
typedef unsigned long long u64;

#define NB   2
#define NN   512
#define IND  512
#define MEMD 300
#define HIDD 64
#define CDIM 428
#define NEG_SLOPE 0.01f
#define GRIDSZ 148
#define NTHR 512
#define TI 32
#define TJ 128

// ---------------- scratch (allocation-free: __device__ globals) -------------
__device__ float g_B1[IND * CDIM];        // [w0 | Wp0]
__device__ float g_B2[MEMD * CDIM];       // [w1 | Wp1]
__device__ float g_bias1[CDIM];
__device__ float g_bias2[CDIM];
__device__ float g_hs[NB * NN * CDIM];    // [h(300) | si(64) | sj(64)]
__device__ float g_out1[NB * NN * MEMD];
__device__ float g_q0[NB * NN * MEMD];    // out-GEMM K-split partials
__device__ float g_q1[NB * NN * MEMD];
__device__ float g_p[NB * NN * NN];
__device__ float g_partial[NB * 64];
__device__ unsigned g_bar_count;
__device__ unsigned g_bar_gen;

// ---------------- grid-wide barrier (replay-safe) ----------------------------
__device__ __forceinline__ void grid_bar(unsigned target)
{
    __threadfence();
    __syncthreads();
    if (threadIdx.x == 0) {
        if (atomicAdd(&g_bar_count, 1u) == GRIDSZ - 1u) {
            g_bar_count = 0u;
            __threadfence();
            *(volatile unsigned*)&g_bar_gen = target;
        } else {
            while ((int)(*(volatile unsigned*)&g_bar_gen - target) < 0) { }
        }
        __threadfence();
    }
    __syncthreads();
}

__device__ __forceinline__ void half_bar(int half)
{
    asm volatile("bar.sync %0, 256;" :: "r"(half + 1) : "memory");
}

// ---------------- cp.async + packed f32 helpers ------------------------------
__device__ __forceinline__ void cpa16(u32 dst, const void* src, bool p)
{
    if (p) asm volatile("cp.async.ca.shared.global [%0], [%1], 16;"
                        :: "r"(dst), "l"(src));
    else   asm volatile("st.shared.v4.b32 [%0], {%1,%1,%1,%1};"
                        :: "r"(dst), "r"(0u));
}
__device__ __forceinline__ void cpa8(u32 dst, const void* src, bool p)
{
    if (p) asm volatile("cp.async.ca.shared.global [%0], [%1], 8;"
                        :: "r"(dst), "l"(src));
    else   asm volatile("st.shared.v2.b32 [%0], {%1,%1};"
                        :: "r"(dst), "r"(0u));
}
__device__ __forceinline__ void cpa_commit()
{
    asm volatile("cp.async.commit_group;" ::: "memory");
}
__device__ __forceinline__ u64 packff(float x, float y)
{
    u64 r;
    asm("mov.b64 %0, {%1, %2};" : "=l"(r)
        : "r"(__float_as_uint(x)), "r"(__float_as_uint(y)));
    return r;
}
__device__ __forceinline__ void fma2(u64& d, u64 a, u64 b)
{
    asm("fma.rn.f32x2 %0, %1, %2, %3;" : "=l"(d) : "l"(a), "l"(b), "l"(d));
}
__device__ __forceinline__ float2 unpk(u64 v)
{
    u32 lo, hi;
    asm("mov.b64 {%0, %1}, %2;" : "=r"(lo), "=r"(hi) : "l"(v));
    return make_float2(__uint_as_float(lo), __uint_as_float(hi));
}

// ---------------- dynamic smem layout ----------------------------------------
// gemm: per half, 3 stages x (As 32x64 f = 8192B | Bs 64x64 f = 16384B) = 73728
// pair overlay (region 0): SiT2[64][17]f2 8704 | SjT[64][129] 33024 | W 256 | red 2048
#define SM_STAGE   24576
#define SM_HALF    73728
#define SM_SJ      8704
#define SM_W       41728
#define SM_RED     41984
#define SM_INVZ    147456
#define SM_DYN     147712

// ---------------- cp.async GEMM: C = A@B (+bias) -----------------------------
// 256-thread half streams, 32x64 tiles, BK=64, 3-stage cp.async pipeline,
// 2x4 micro with packed f32x2 FMAs. KSPLIT=2 writes unscaled partials to C0/C1.
template<int BVIEW, int KSPLIT>
__device__ void gemm_cp(char* SMD, int half, int ghalf,
                        const float* __restrict__ A, long long sA, int ldA,
                        const float* __restrict__ B, long long sB, int ldB,
                        float* __restrict__ C0, float* __restrict__ C1,
                        long long sC, int ldC,
                        int M, int Ncols, int K, int batches,
                        const float* __restrict__ bias)
{
    char* hb  = SMD + half * SM_HALF;
    u32 hb32  = (u32)__cvta_generic_to_shared(hb);
    int lid = threadIdx.x & 255;
    int tx = lid & 15, ty = lid >> 4;

    int colT = (Ncols + 63) >> 6;
    int rowT = (M + 31) >> 5;
    int TT   = colT * rowT * batches * KSPLIT;
    int Klen = K / KSPLIT;
    int nkt  = (Klen + 63) >> 6;

    for (int t = ghalf; t < TT; t += 2 * GRIDSZ) {
        int ks = (KSPLIT == 2) ? (t & 1) : 0;
        int t2 = (KSPLIT == 2) ? (t >> 1) : t;
        int bz  = t2 / (colT * rowT);
        int r2  = t2 - bz * (colT * rowT);
        int byy = r2 / colT, bxx = r2 - byy * colT;
        int row0 = byy * 32, col0 = bxx * 64;
        int kbase = ks * Klen;

        const float* Ab = A + (long long)bz * sA;
        const float* Bb;
        int colB;
        if (BVIEW) { Bb = B + (col0 >= 64 ? MEMD * 64 : 0); colB = col0 & 63; }
        else       { Bb = B + (long long)bz * sB;           colB = col0; }
        float* Cb = (ks ? C1 : C0) + (long long)bz * sC;

        auto issue = [&](int stage, int kt) {
            u32 sb = hb32 + stage * SM_STAGE;
            int kg = kbase + kt * 64;
            #pragma unroll
            for (int q = 0; q < 4; q++) {          // A: 32 rows x 64 k, 8B chunks
                int idx = lid + q * 256;
                int rr = idx >> 5, kc = (idx & 31) * 2;
                int k = kg + kc;
                bool p = (k < K) && (row0 + rr < M);
                cpa8(sb + rr * 256 + kc * 4,
                     Ab + (long long)(row0 + rr) * ldA + k, p);
            }
            #pragma unroll
            for (int q = 0; q < 4; q++) {          // B: 64 k x 64 cols, 16B chunks
                int idx = lid + q * 256;
                int kk = idx >> 4, c4 = (idx & 15) * 4;
                int k = kg + kk;
                bool p = (k < K) && (col0 + c4 < Ncols);
                cpa16(sb + 8192 + kk * 256 + c4 * 4,
                      Bb + (long long)k * ldB + colB + c4, p);
            }
            cpa_commit();
        };

        // prologue: stages 0,1
        issue(0, 0);
        if (nkt > 1) issue(1, 1);

        u64 acc0 = 0, acc1 = 0, acc2 = 0, acc3 = 0;

        for (int kt = 0; kt < nkt; kt++) {
            if (kt < nkt - 1) asm volatile("cp.async.wait_group 1;" ::: "memory");
            else              asm volatile("cp.async.wait_group 0;" ::: "memory");
            half_bar(half);
            if (kt + 2 < nkt) issue((kt + 2) % 3, kt + 2);

            const float* Asf = (const float*)(hb + (kt % 3) * SM_STAGE);
            const float* Bsf = Asf + 2048;
            #pragma unroll 16
            for (int kk = 0; kk < 64; kk++) {
                float a0 = Asf[ty * 64 + kk];
                float a1 = Asf[(ty + 16) * 64 + kk];
                u64 b01 = *(const u64*)&Bsf[kk * 64 + tx * 4];
                u64 b23 = *(const u64*)&Bsf[kk * 64 + tx * 4 + 2];
                u64 a0p = packff(a0, a0), a1p = packff(a1, a1);
                fma2(acc0, a0p, b01); fma2(acc1, a0p, b23);
                fma2(acc2, a1p, b01); fma2(acc3, a1p, b23);
            }
        }
        half_bar(half);   // protect stages from next tile's prologue

        // epilogue
        float2 r01 = unpk(acc0), r23 = unpk(acc1);
        float2 r45 = unpk(acc2), r67 = unpk(acc3);
        float v0[4] = {r01.x, r01.y, r23.x, r23.y};
        float v1[4] = {r45.x, r45.y, r67.x, r67.y};
        int c0 = col0 + tx * 4;
        int rr0 = row0 + ty, rr1 = row0 + ty + 16;
        #pragma unroll
        for (int j = 0; j < 4; j++) {
            int cc = c0 + j;
            if (cc < Ncols) {
                float bv = bias ? bias[cc] : 0.f;
                if (rr0 < M) Cb[(long long)rr0 * ldC + cc] = v0[j] + bv;
                if (rr1 < M) Cb[(long long)rr1 * ldC + cc] = v1[j] + bv;
            }
        }
    }
}

// ---------------- pairwise: p = adj*exp(leaky(e)), partial Z -----------------
__device__ void pair_phase(char* SMD,
                           const float* __restrict__ adj,
                           const float* __restrict__ a2w,
                           const float* __restrict__ a2b)
{
    float2 (*SiT2)[17]    = (float2(*)[17])SMD;
    float  (*SjT)[TJ + 1] = (float(*)[TJ + 1])(SMD + SM_SJ);
    float* W   = (float*)(SMD + SM_W);
    float* red = (float*)(SMD + SM_RED);

    int tid = threadIdx.x;
    int tx = tid & 31, ty = (tid >> 5) & 15;
    const int Tt = NB * (NN / TI) * (NN / TJ);   // 128

    for (int t = blockIdx.x; t < Tt; t += GRIDSZ) {
        int b = t >> 6;
        int rem = t & 63;
        int by = rem >> 2, bx = rem & 3;
        int i0 = by * TI, j0 = bx * TJ;

        __syncthreads();
        for (int idx = tid; idx < HIDD * 16; idx += NTHR) {
            int h = idx & 63, rr = idx >> 6;
            float u0 = g_hs[((long long)(b * NN) + i0 + rr) * CDIM + 300 + h];
            float u1 = g_hs[((long long)(b * NN) + i0 + rr + 16) * CDIM + 300 + h];
            SiT2[h][rr] = make_float2(u0, u1);
        }
        for (int idx = tid; idx < HIDD * TJ; idx += NTHR) {
            int h = idx & 63, rr = idx >> 6;
            SjT[h][rr] = g_hs[((long long)(b * NN) + j0 + rr) * CDIM + 364 + h];
        }
        if (tid < HIDD) W[tid] = a2w[tid];
        __syncthreads();

        float acc[8] = {0.f, 0.f, 0.f, 0.f, 0.f, 0.f, 0.f, 0.f};
        #pragma unroll 8
        for (int h = 0; h < HIDD; h++) {
            float w = W[h];
            float2 ai = SiT2[h][ty];
            float bj[4];
            #pragma unroll
            for (int jj = 0; jj < 4; jj++) bj[jj] = SjT[h][tx + 32 * jj];
            #pragma unroll
            for (int jj = 0; jj < 4; jj++) {
                float x0 = ai.x + bj[jj];
                float x1 = ai.y + bj[jj];
                acc[jj]     += fmaxf(x0, 0.f) * w;
                acc[4 + jj] += fmaxf(x1, 0.f) * w;
            }
        }

        float a2bv = a2b[0];
        float psum = 0.f;
        int ia = i0 + ty, ib = i0 + ty + 16;
        #pragma unroll
        for (int jj = 0; jj < 4; jj++) {
            int j = j0 + tx + 32 * jj;
            float e0 = acc[jj] + a2bv;
            float e1 = acc[4 + jj] + a2bv;
            e0 = e0 > 0.f ? e0 : NEG_SLOPE * e0;
            e1 = e1 > 0.f ? e1 : NEG_SLOPE * e1;
            float ad0 = adj[((long long)b * NN + ia) * NN + j];
            float ad1 = adj[((long long)b * NN + ib) * NN + j];
            float p0 = ad0 * __expf(e0);
            float p1 = ad1 * __expf(e1);
            g_p[((long long)b * NN + ia) * NN + j] = p0;
            g_p[((long long)b * NN + ib) * NN + j] = p1;
            psum += p0 + p1;
        }

        red[tid] = psum;
        __syncthreads();
        for (int s = 256; s > 0; s >>= 1) {
            if (tid < s) red[tid] += red[tid + s];
            __syncthreads();
        }
        if (tid == 0) g_partial[b * 64 + rem] = red[0];
    }
}

// ---------------- combine: dst = (q0+q1) * invZ[b] ---------------------------
__device__ void combine_phase(char* SMD, const float* __restrict__ q0,
                              const float* __restrict__ q1,
                              float* __restrict__ dst)
{
    float* invZ = (float*)(SMD + SM_INVZ);
    int tid = threadIdx.x;
    if (tid < NB) {
        float s = 0.f;
        #pragma unroll
        for (int k = 0; k < 64; k++) s += g_partial[tid * 64 + k];
        invZ[tid] = 1.f / s;
    }
    __syncthreads();
    float z0 = invZ[0], z1 = invZ[1];
    const int TOT = NB * NN * MEMD;
    for (int i = blockIdx.x * NTHR + tid; i < TOT; i += GRIDSZ * NTHR) {
        float z = (i < NN * MEMD) ? z0 : z1;
        dst[i] = (q0[i] + q1[i]) * z;
    }
}

// ---------------- the one persistent kernel ----------------------------------
__global__ void __launch_bounds__(NTHR, 1) fused_gat(
    const float* __restrict__ feature, const float* __restrict__ adj,
    const float* __restrict__ w0, const float* __restrict__ b0,
    const float* __restrict__ w1, const float* __restrict__ b1,
    const float* __restrict__ a1w, const float* __restrict__ a1b,
    const float* __restrict__ a2w, const float* __restrict__ a2b,
    float* __restrict__ out)
{
    extern __shared__ char SMD[];
    __shared__ unsigned s_base;
    if (threadIdx.x == 0) s_base = *(volatile unsigned*)&g_bar_gen;
    __syncthreads();
    unsigned bb = s_base;
    int half  = threadIdx.x >> 8;
    int ghalf = half * GRIDSZ + blockIdx.x;   // 0..295
    int tid = threadIdx.x;

    // ======== P0: B' = [W | W@a1w-packed], bias vectors ========
    for (int idx = blockIdx.x * NTHR + tid; idx < IND * MEMD; idx += GRIDSZ * NTHR) {
        int r = idx / MEMD, c = idx - r * MEMD;
        g_B1[r * CDIM + c] = w0[idx];
    }
    for (int idx = blockIdx.x * NTHR + tid; idx < MEMD * MEMD; idx += GRIDSZ * NTHR) {
        int r = idx / MEMD, c = idx - r * MEMD;
        g_B2[r * CDIM + c] = w1[idx];
    }
    if (blockIdx.x < 2) {
        const float* bsrc = blockIdx.x ? b1 : b0;
        float* bd = blockIdx.x ? g_bias2 : g_bias1;
        for (int c = tid; c < MEMD; c += NTHR) bd[c] = bsrc[c];
        if (tid < 128) {
            float acc = 0.f;
            for (int k = 0; k < MEMD; k++) {
                float w = (tid < 64) ? a1w[k * 64 + tid]
                                     : a1w[(MEMD + k) * 64 + (tid - 64)];
                acc += bsrc[k] * w;
            }
            bd[300 + tid] = acc + ((tid >= 64) ? a1b[tid - 64] : 0.f);
        }
    }
    // Wp0 on low halves, Wp1 on high halves (disjoint)
    gemm_cp<1, 1>(SMD, half, ghalf, w0, 0, MEMD, a1w, 0, 64,
                  g_B1 + 300, nullptr, 0, CDIM, IND, 128, MEMD, 1, nullptr);
    gemm_cp<1, 1>(SMD, half, 295 - ghalf, w1, 0, MEMD, a1w, 0, 64,
                  g_B2 + 300, nullptr, 0, CDIM, MEMD, 128, MEMD, 1, nullptr);
    grid_bar(bb + 1);

    // ======== layer 1 ========
    gemm_cp<0, 1>(SMD, half, ghalf, feature, 0, IND, g_B1, 0, CDIM,
                  g_hs, nullptr, 0, CDIM, NB * NN, CDIM, IND, 1, g_bias1);
    grid_bar(bb + 2);
    pair_phase(SMD, adj, a2w, a2b);
    grid_bar(bb + 3);
    gemm_cp<0, 2>(SMD, half, ghalf, g_p, (long long)NN * NN, NN,
                  g_hs, (long long)NN * CDIM, CDIM,
                  g_q0, g_q1, (long long)NN * MEMD, MEMD,
                  NN, MEMD, NN, NB, nullptr);
    grid_bar(bb + 4);
    combine_phase(SMD, g_q0, g_q1, g_out1);
    grid_bar(bb + 5);

    // ======== layer 2 ========
    gemm_cp<0, 1>(SMD, half, ghalf, g_out1, 0, MEMD, g_B2, 0, CDIM,
                  g_hs, nullptr, 0, CDIM, NB * NN, CDIM, MEMD, 1, g_bias2);
    grid_bar(bb + 6);
    pair_phase(SMD, adj, a2w, a2b);
    grid_bar(bb + 7);
    gemm_cp<0, 2>(SMD, half, ghalf, g_p, (long long)NN * NN, NN,
                  g_hs, (long long)NN * CDIM, CDIM,
                  g_q0, g_q1, (long long)NN * MEMD, MEMD,
                  NN, MEMD, NN, NB, nullptr);
    grid_bar(bb + 8);
    combine_phase(SMD, g_q0, g_q1, out);
}

// ---------------- host launcher ----------------------------------------------
extern "C" void kernel_launch(void* const* d_in, const int* in_sizes, int n_in,
                              void* d_out, int out_size)
{
    const float* feature = (const float*)d_in[0];
    const float* adj     = (const float*)d_in[1];
    const float* w0      = (const float*)d_in[2];
    const float* b0      = (const float*)d_in[3];
    const float* w1      = (const float*)d_in[4];
    const float* b1      = (const float*)d_in[5];
    const float* a1w     = (const float*)d_in[6];
    const float* a1b     = (const float*)d_in[7];
    const float* a2w     = (const float*)d_in[8];
    const float* a2b     = (const float*)d_in[9];
    float* out = (float*)d_out;

    static bool attr_set = false;
    if (!attr_set) {
        cudaFuncSetAttribute(fused_gat,
                             cudaFuncAttributeMaxDynamicSharedMemorySize, SM_DYN);
        attr_set = true;
    }
    fused_gat<<<GRIDSZ, NTHR, SM_DYN>>>(feature, adj, w0, b0, w1, b1,
                                        a1w, a1b, a2w, a2b, out);
}

// round 10
// speedup vs baseline: 2.0388x; 1.0573x over previous
#include <cuda_runtime.h>

typedef unsigned int       u32;
typedef unsigned long long u64;

#define NB   2
#define NN   512
#define IND  512
#define MEMD 300
#define HIDD 64
#define CDIM 428
#define NEG_SLOPE 0.01f
#define GRIDSZ 148
#define NTHR 512
#define NSTREAM (4 * GRIDSZ)      // 128-thread quarter streams
#define TI 32
#define TJ 128

// ---------------- scratch (allocation-free: __device__ globals) -------------
__device__ float g_B1[IND * CDIM];        // [w0 | Wp0]
__device__ float g_B2[MEMD * CDIM];       // [w1 | Wp1]
__device__ float g_bias1[CDIM];
__device__ float g_bias2[CDIM];
__device__ float g_hs[NB * NN * CDIM];    // [h(300) | si(64) | sj(64)]
__device__ float g_out1[NB * NN * MEMD];
__device__ float g_q0[NB * NN * MEMD];    // out-GEMM K-split partials
__device__ float g_q1[NB * NN * MEMD];
__device__ float g_p[NB * NN * NN];
__device__ float g_partial[NB * 64];
__device__ unsigned g_bar_count;
__device__ unsigned g_bar_gen;

// ---------------- grid-wide barrier (replay-safe) ----------------------------
__device__ __forceinline__ void grid_bar(unsigned target)
{
    __threadfence();
    __syncthreads();
    if (threadIdx.x == 0) {
        if (atomicAdd(&g_bar_count, 1u) == GRIDSZ - 1u) {
            g_bar_count = 0u;
            __threadfence();
            *(volatile unsigned*)&g_bar_gen = target;
        } else {
            while ((int)(*(volatile unsigned*)&g_bar_gen - target) < 0) { }
        }
        __threadfence();
    }
    __syncthreads();
}

// per-quarter named barrier (128 threads; ids 1..4)
__device__ __forceinline__ void qbar(int q)
{
    asm volatile("bar.sync %0, 128;" :: "r"(q + 1) : "memory");
}

// ---------------- cp.async + packed f32 helpers ------------------------------
__device__ __forceinline__ void cpa16(u32 dst, const void* src, bool p)
{
    if (p) asm volatile("cp.async.ca.shared.global [%0], [%1], 16;"
                        :: "r"(dst), "l"(src));
    else   asm volatile("st.shared.v4.b32 [%0], {%1,%1,%1,%1};"
                        :: "r"(dst), "r"(0u));
}
__device__ __forceinline__ void cpa8(u32 dst, const void* src, bool p)
{
    if (p) asm volatile("cp.async.ca.shared.global [%0], [%1], 8;"
                        :: "r"(dst), "l"(src));
    else   asm volatile("st.shared.v2.b32 [%0], {%1,%1};"
                        :: "r"(dst), "r"(0u));
}
__device__ __forceinline__ void cpa_commit()
{
    asm volatile("cp.async.commit_group;" ::: "memory");
}
__device__ __forceinline__ void cpa_wait1()
{
    asm volatile("cp.async.wait_group 1;" ::: "memory");
}
__device__ __forceinline__ void cpa_wait0()
{
    asm volatile("cp.async.wait_group 0;" ::: "memory");
}
__device__ __forceinline__ u64 packff(float x, float y)
{
    u64 r;
    asm("mov.b64 %0, {%1, %2};" : "=l"(r)
        : "r"(__float_as_uint(x)), "r"(__float_as_uint(y)));
    return r;
}
__device__ __forceinline__ void fma2(u64& d, u64 a, u64 b)
{
    asm("fma.rn.f32x2 %0, %1, %2, %3;" : "=l"(d) : "l"(a), "l"(b), "l"(d));
}
__device__ __forceinline__ float2 unpk(u64 v)
{
    u32 lo, hi;
    asm("mov.b64 {%0, %1}, %2;" : "=r"(lo), "=r"(hi) : "l"(v));
    return make_float2(__uint_as_float(lo), __uint_as_float(hi));
}
// LDS.128 -> two u64 (register-pair friendly for FFMA2)
__device__ __forceinline__ void lds_v2u64(u64& x, u64& y, const float* p)
{
    u32 a = (u32)__cvta_generic_to_shared(p);
    asm volatile("ld.shared.v2.b64 {%0, %1}, [%2];"
                 : "=l"(x), "=l"(y) : "r"(a));
}

// ---------------- dynamic smem layout ----------------------------------------
// per quarter: 2 stages x (A 32x66 f = 8448B | B 64x64 f = 16384B) = 49664
// pair overlay reuses region from offset 0.
#define SM_A_BYTES 8448
#define SM_STAGE   24832
#define SM_QUARTER 49664
#define SM_SJ      8704
#define SM_W       41728
#define SM_RED     41984
#define SM_INVZ    (4 * SM_QUARTER)
#define SM_DYN     (SM_INVZ + 256)

// ---------------- cp.async GEMM (quarter streams) ----------------------------
// 128-thread quarter computes 32x64 tiles, BK=64, 2-stage pipeline,
// 2x8 micro with packed f32x2 FMAs. KSPLIT=2 -> unscaled partials C0/C1.
template<int BVIEW, int KSPLIT>
__device__ void gemm_cp(char* SMD, int q, int qid,
                        const float* __restrict__ A, long long sA, int ldA,
                        const float* __restrict__ B, long long sB, int ldB,
                        float* __restrict__ C0, float* __restrict__ C1,
                        long long sC, int ldC,
                        int M, int Ncols, int K, int batches,
                        const float* __restrict__ bias)
{
    char* qb = SMD + q * SM_QUARTER;
    u32 qb32 = (u32)__cvta_generic_to_shared(qb);
    int lid = threadIdx.x & 127;
    int tx = lid & 7, ty = lid >> 3;          // 8 x 16

    int colT = (Ncols + 63) >> 6;
    int rowT = (M + 31) >> 5;
    int TT   = colT * rowT * batches * KSPLIT;
    int Klen = K / KSPLIT;
    int nkt  = (Klen + 63) >> 6;

    for (int t = qid; t < TT; t += NSTREAM) {
        int ks = (KSPLIT == 2) ? (t & 1) : 0;
        int t2 = (KSPLIT == 2) ? (t >> 1) : t;
        int bz  = t2 / (colT * rowT);
        int r2  = t2 - bz * (colT * rowT);
        int byy = r2 / colT, bxx = r2 - byy * colT;
        int row0 = byy * 32, col0 = bxx * 64;
        int kbase = ks * Klen;

        const float* Ab = A + (long long)bz * sA;
        const float* Bb;
        int colB;
        if (BVIEW) { Bb = B + (col0 >= 64 ? MEMD * 64 : 0); colB = col0 & 63; }
        else       { Bb = B + (long long)bz * sB;           colB = col0; }
        float* Cb = (ks ? C1 : C0) + (long long)bz * sC;

        auto issue = [&](int stage, int kt) {
            u32 sb = qb32 + stage * SM_STAGE;
            int kg = kbase + kt * 64;
            #pragma unroll
            for (int g = 0; g < 8; g++) {          // A: 32 rows x 64 k, 8B chunks
                int idx = lid + g * 128;
                int rr = idx >> 5, kc = (idx & 31) * 2;
                int k = kg + kc;
                bool p = (k < K) && (row0 + rr < M);
                cpa8(sb + rr * 264 + kc * 4,
                     Ab + (long long)(row0 + rr) * ldA + k, p);
            }
            #pragma unroll
            for (int g = 0; g < 8; g++) {          // B: 64 k x 64 cols, 16B chunks
                int idx = lid + g * 128;
                int kk = idx >> 4, c4 = (idx & 15) * 4;
                int k = kg + kk;
                bool p = (k < K) && (col0 + c4 < Ncols);
                cpa16(sb + SM_A_BYTES + kk * 256 + c4 * 4,
                      Bb + (long long)k * ldB + colB + c4, p);
            }
            cpa_commit();
        };

        issue(0, 0);

        u64 acc[8];
        #pragma unroll
        for (int i = 0; i < 8; i++) acc[i] = 0;

        for (int kt = 0; kt < nkt; kt++) {
            bool more = (kt + 1 < nkt);
            if (more) issue((kt + 1) & 1, kt + 1);
            if (more) cpa_wait1(); else cpa_wait0();
            qbar(q);

            const float* Asf = (const float*)(qb + (kt & 1) * SM_STAGE);
            const float* Bsf = Asf + SM_A_BYTES / 4;
            #pragma unroll 8
            for (int kp = 0; kp < 32; kp++) {
                float2 a0 = *(const float2*)&Asf[ty * 66 + kp * 2];
                float2 a1 = *(const float2*)&Asf[(ty + 16) * 66 + kp * 2];
                u64 b00a, b00b, b01a, b01b, b10a, b10b, b11a, b11b;
                lds_v2u64(b00a, b00b, &Bsf[(kp * 2) * 64 + tx * 4]);
                lds_v2u64(b01a, b01b, &Bsf[(kp * 2) * 64 + 32 + tx * 4]);
                lds_v2u64(b10a, b10b, &Bsf[(kp * 2 + 1) * 64 + tx * 4]);
                lds_v2u64(b11a, b11b, &Bsf[(kp * 2 + 1) * 64 + 32 + tx * 4]);
                u64 ax0 = packff(a0.x, a0.x), ax1 = packff(a1.x, a1.x);
                u64 ay0 = packff(a0.y, a0.y), ay1 = packff(a1.y, a1.y);
                fma2(acc[0], ax0, b00a); fma2(acc[1], ax0, b00b);
                fma2(acc[2], ax0, b01a); fma2(acc[3], ax0, b01b);
                fma2(acc[4], ax1, b00a); fma2(acc[5], ax1, b00b);
                fma2(acc[6], ax1, b01a); fma2(acc[7], ax1, b01b);
                fma2(acc[0], ay0, b10a); fma2(acc[1], ay0, b10b);
                fma2(acc[2], ay0, b11a); fma2(acc[3], ay0, b11b);
                fma2(acc[4], ay1, b10a); fma2(acc[5], ay1, b10b);
                fma2(acc[6], ay1, b11a); fma2(acc[7], ay1, b11b);
            }
            qbar(q);
        }

        // epilogue: rows ty, ty+16; cols col0 + g*32 + tx*4 + {0..3}
        #pragma unroll
        for (int r = 0; r < 2; r++) {
            int row = row0 + ty + r * 16;
            if (row >= M) continue;
            #pragma unroll
            for (int g = 0; g < 2; g++) {
                int cbase = col0 + g * 32 + tx * 4;
                float2 lo = unpk(acc[r * 4 + g * 2]);
                float2 hi = unpk(acc[r * 4 + g * 2 + 1]);
                float v[4] = {lo.x, lo.y, hi.x, hi.y};
                #pragma unroll
                for (int j = 0; j < 4; j++) {
                    int cc = cbase + j;
                    if (cc < Ncols) {
                        float bv = bias ? bias[cc] : 0.f;
                        Cb[(long long)row * ldC + cc] = v[j] + bv;
                    }
                }
            }
        }
    }
}

// ---------------- pairwise: p = adj*exp(leaky(e)), partial Z -----------------
__device__ void pair_phase(char* SMD,
                           const float* __restrict__ adj,
                           const float* __restrict__ a2w,
                           const float* __restrict__ a2b)
{
    float2 (*SiT2)[17]    = (float2(*)[17])SMD;
    float  (*SjT)[TJ + 1] = (float(*)[TJ + 1])(SMD + SM_SJ);
    float* W   = (float*)(SMD + SM_W);
    float* red = (float*)(SMD + SM_RED);

    int tid = threadIdx.x;
    int tx = tid & 31, ty = (tid >> 5) & 15;
    const int Tt = NB * (NN / TI) * (NN / TJ);   // 128

    for (int t = blockIdx.x; t < Tt; t += GRIDSZ) {
        int b = t >> 6;
        int rem = t & 63;
        int by = rem >> 2, bx = rem & 3;
        int i0 = by * TI, j0 = bx * TJ;

        __syncthreads();
        for (int idx = tid; idx < HIDD * 16; idx += NTHR) {
            int h = idx & 63, rr = idx >> 6;
            float u0 = g_hs[((long long)(b * NN) + i0 + rr) * CDIM + 300 + h];
            float u1 = g_hs[((long long)(b * NN) + i0 + rr + 16) * CDIM + 300 + h];
            SiT2[h][rr] = make_float2(u0, u1);
        }
        for (int idx = tid; idx < HIDD * TJ; idx += NTHR) {
            int h = idx & 63, rr = idx >> 6;
            SjT[h][rr] = g_hs[((long long)(b * NN) + j0 + rr) * CDIM + 364 + h];
        }
        if (tid < HIDD) W[tid] = a2w[tid];
        __syncthreads();

        float acc[8] = {0.f, 0.f, 0.f, 0.f, 0.f, 0.f, 0.f, 0.f};
        #pragma unroll 8
        for (int h = 0; h < HIDD; h++) {
            float w = W[h];
            float2 ai = SiT2[h][ty];
            float bj[4];
            #pragma unroll
            for (int jj = 0; jj < 4; jj++) bj[jj] = SjT[h][tx + 32 * jj];
            #pragma unroll
            for (int jj = 0; jj < 4; jj++) {
                float x0 = ai.x + bj[jj];
                float x1 = ai.y + bj[jj];
                acc[jj]     += fmaxf(x0, 0.f) * w;
                acc[4 + jj] += fmaxf(x1, 0.f) * w;
            }
        }

        float a2bv = a2b[0];
        float psum = 0.f;
        int ia = i0 + ty, ib = i0 + ty + 16;
        #pragma unroll
        for (int jj = 0; jj < 4; jj++) {
            int j = j0 + tx + 32 * jj;
            float e0 = acc[jj] + a2bv;
            float e1 = acc[4 + jj] + a2bv;
            e0 = e0 > 0.f ? e0 : NEG_SLOPE * e0;
            e1 = e1 > 0.f ? e1 : NEG_SLOPE * e1;
            float ad0 = adj[((long long)b * NN + ia) * NN + j];
            float ad1 = adj[((long long)b * NN + ib) * NN + j];
            float p0 = ad0 * __expf(e0);
            float p1 = ad1 * __expf(e1);
            g_p[((long long)b * NN + ia) * NN + j] = p0;
            g_p[((long long)b * NN + ib) * NN + j] = p1;
            psum += p0 + p1;
        }

        red[tid] = psum;
        __syncthreads();
        for (int s = 256; s > 0; s >>= 1) {
            if (tid < s) red[tid] += red[tid + s];
            __syncthreads();
        }
        if (tid == 0) g_partial[b * 64 + rem] = red[0];
    }
}

// ---------------- combine: dst = (q0+q1) * invZ[b] ---------------------------
__device__ void combine_phase(char* SMD, const float* __restrict__ q0,
                              const float* __restrict__ q1,
                              float* __restrict__ dst)
{
    float* invZ = (float*)(SMD + SM_INVZ);
    int tid = threadIdx.x;
    if (tid < NB) {
        float s = 0.f;
        #pragma unroll
        for (int k = 0; k < 64; k++) s += g_partial[tid * 64 + k];
        invZ[tid] = 1.f / s;
    }
    __syncthreads();
    float z0 = invZ[0], z1 = invZ[1];
    const int TOT = NB * NN * MEMD;
    for (int i = blockIdx.x * NTHR + tid; i < TOT; i += GRIDSZ * NTHR) {
        float z = (i < NN * MEMD) ? z0 : z1;
        dst[i] = (q0[i] + q1[i]) * z;
    }
}

// ---------------- the one persistent kernel ----------------------------------
__global__ void __launch_bounds__(NTHR, 1) fused_gat(
    const float* __restrict__ feature, const float* __restrict__ adj,
    const float* __restrict__ w0, const float* __restrict__ b0,
    const float* __restrict__ w1, const float* __restrict__ b1,
    const float* __restrict__ a1w, const float* __restrict__ a1b,
    const float* __restrict__ a2w, const float* __restrict__ a2b,
    float* __restrict__ out)
{
    extern __shared__ char SMD[];
    __shared__ unsigned s_base;
    if (threadIdx.x == 0) s_base = *(volatile unsigned*)&g_bar_gen;
    __syncthreads();
    unsigned bb = s_base;
    int q   = threadIdx.x >> 7;               // quarter 0..3
    int qid = q * GRIDSZ + blockIdx.x;        // 0..591
    int tid = threadIdx.x;

    // ======== P0: B' = [W | W@a1w-packed], bias vectors ========
    for (int idx = blockIdx.x * NTHR + tid; idx < IND * MEMD; idx += GRIDSZ * NTHR) {
        int r = idx / MEMD, c = idx - r * MEMD;
        g_B1[r * CDIM + c] = w0[idx];
    }
    for (int idx = blockIdx.x * NTHR + tid; idx < MEMD * MEMD; idx += GRIDSZ * NTHR) {
        int r = idx / MEMD, c = idx - r * MEMD;
        g_B2[r * CDIM + c] = w1[idx];
    }
    if (blockIdx.x < 2) {
        const float* bsrc = blockIdx.x ? b1 : b0;
        float* bd = blockIdx.x ? g_bias2 : g_bias1;
        for (int c = tid; c < MEMD; c += NTHR) bd[c] = bsrc[c];
        if (tid < 128) {
            float acc = 0.f;
            for (int k = 0; k < MEMD; k++) {
                float w = (tid < 64) ? a1w[k * 64 + tid]
                                     : a1w[(MEMD + k) * 64 + (tid - 64)];
                acc += bsrc[k] * w;
            }
            bd[300 + tid] = acc + ((tid >= 64) ? a1b[tid - 64] : 0.f);
        }
    }
    // Wp0 on low quarters, Wp1 on high quarters (disjoint)
    gemm_cp<1, 1>(SMD, q, qid, w0, 0, MEMD, a1w, 0, 64,
                  g_B1 + 300, nullptr, 0, CDIM, IND, 128, MEMD, 1, nullptr);
    gemm_cp<1, 1>(SMD, q, (NSTREAM - 1) - qid, w1, 0, MEMD, a1w, 0, 64,
                  g_B2 + 300, nullptr, 0, CDIM, MEMD, 128, MEMD, 1, nullptr);
    grid_bar(bb + 1);

    // ======== layer 1 ========
    gemm_cp<0, 1>(SMD, q, qid, feature, 0, IND, g_B1, 0, CDIM,
                  g_hs, nullptr, 0, CDIM, NB * NN, CDIM, IND, 1, g_bias1);
    grid_bar(bb + 2);
    pair_phase(SMD, adj, a2w, a2b);
    grid_bar(bb + 3);
    gemm_cp<0, 2>(SMD, q, qid, g_p, (long long)NN * NN, NN,
                  g_hs, (long long)NN * CDIM, CDIM,
                  g_q0, g_q1, (long long)NN * MEMD, MEMD,
                  NN, MEMD, NN, NB, nullptr);
    grid_bar(bb + 4);
    combine_phase(SMD, g_q0, g_q1, g_out1);
    grid_bar(bb + 5);

    // ======== layer 2 ========
    gemm_cp<0, 1>(SMD, q, qid, g_out1, 0, MEMD, g_B2, 0, CDIM,
                  g_hs, nullptr, 0, CDIM, NB * NN, CDIM, MEMD, 1, g_bias2);
    grid_bar(bb + 6);
    pair_phase(SMD, adj, a2w, a2b);
    grid_bar(bb + 7);
    gemm_cp<0, 2>(SMD, q, qid, g_p, (long long)NN * NN, NN,
                  g_hs, (long long)NN * CDIM, CDIM,
                  g_q0, g_q1, (long long)NN * MEMD, MEMD,
                  NN, MEMD, NN, NB, nullptr);
    grid_bar(bb + 8);
    combine_phase(SMD, g_q0, g_q1, out);
}

// ---------------- host launcher ----------------------------------------------
extern "C" void kernel_launch(void* const* d_in, const int* in_sizes, int n_in,
                              void* d_out, int out_size)
{
    const float* feature = (const float*)d_in[0];
    const float* adj     = (const float*)d_in[1];
    const float* w0      = (const float*)d_in[2];
    const float* b0      = (const float*)d_in[3];
    const float* w1      = (const float*)d_in[4];
    const float* b1      = (const float*)d_in[5];
    const float* a1w     = (const float*)d_in[6];
    const float* a1b     = (const float*)d_in[7];
    const float* a2w     = (const float*)d_in[8];
    const float* a2b     = (const float*)d_in[9];
    float* out = (float*)d_out;

    static bool attr_set = false;
    if (!attr_set) {
        cudaFuncSetAttribute(fused_gat,
                             cudaFuncAttributeMaxDynamicSharedMemorySize, SM_DYN);
        attr_set = true;
    }
    fused_gat<<<GRIDSZ, NTHR, SM_DYN>>>(feature, adj, w0, b0, w1, b1,
                                        a1w, a1b, a2w, a2b, out);
}